// round 15
// baseline (speedup 1.0000x reference)
#include <cuda_runtime.h>
#include <cuda_bf16.h>
#include <mma.h>
#include <cstdint>

using namespace nvcuda;

#define N_NODES 50000
#define N_PAD   50048            // padded rows so full-tile stores stay in-bounds
#define N_EDGES 800000
#define HID 256
#define OUTC 128
#define NEG_SLOPE 0.2f

// ---------------- scratch (device globals; no allocations allowed) ----------
__device__ float g_H[(size_t)N_PAD * HID];      // layer-1 GEMM output
__device__ float g_H2[(size_t)N_PAD * OUTC];    // layer-2 GEMM output
__device__ float g_X1[(size_t)N_PAD * HID];     // layer-1 output
__device__ float g_asrc[N_NODES];
__device__ float g_adst[N_NODES];
__device__ float g_max[N_NODES];
__device__ float g_sum[N_NODES];                // holds 1/(s+eps)
__device__ float g_e[N_EDGES];                  // per-edge logits (CSR order)
__device__ float g_v1[2 * HID];                 // layer-1 v_src | v_dst
__device__ float g_v2[2 * HID];                 // layer-2 v_src | v_dst
__device__ __nv_bfloat16 g_Bh1[256 * 256];      // W1^T hi (bf16, [N][K] K-major)
__device__ __nv_bfloat16 g_Bl1[256 * 256];      // W1^T lo
__device__ __nv_bfloat16 g_Bh2[256 * 256];      // W2^T hi
__device__ __nv_bfloat16 g_Bl2[256 * 256];      // W2^T lo
// CSR (built once per launch; shared by both layers)
__device__ int g_deg[N_NODES];
__device__ int g_off[N_NODES + 1];
__device__ int g_pos[N_NODES];
__device__ int g_srcs[N_EDGES];                 // src node per dst-sorted slot

__device__ __forceinline__ float leaky(float e) {
    return (e > 0.0f) ? e : NEG_SLOPE * e;
}

__device__ __forceinline__ void cp_async16(uint32_t dst_smem, const void* src) {
    asm volatile("cp.async.cg.shared.global [%0], [%1], 16;"
                 :: "r"(dst_smem), "l"(src));
}

// ---------------- CSR build --------------------------------------------------
__global__ void zero_deg_kernel() {
    int i = blockIdx.x * blockDim.x + threadIdx.x;
    if (i < N_NODES) g_deg[i] = 0;
}

__global__ void hist_kernel(const int* __restrict__ ei) {
    int i = blockIdx.x * blockDim.x + threadIdx.x;
    if (i >= N_EDGES) return;
    atomicAdd(&g_deg[ei[N_EDGES + i]], 1);
}

__global__ void scan_kernel() {
    __shared__ int partial[1024];
    const int t = threadIdx.x;
    const int CH = (N_NODES + 1023) / 1024;
    int b = t * CH;
    int e = b + CH; if (e > N_NODES) e = N_NODES;
    int s = 0;
    for (int i = b; i < e; i++) s += g_deg[i];
    partial[t] = s;
    __syncthreads();
    for (int off = 1; off < 1024; off <<= 1) {
        int v = (t >= off) ? partial[t - off] : 0;
        __syncthreads();
        partial[t] += v;
        __syncthreads();
    }
    int run = (t > 0) ? partial[t - 1] : 0;
    for (int i = b; i < e; i++) {
        int d = g_deg[i];
        g_off[i] = run;
        g_pos[i] = run;
        run += d;
    }
    if (t == 1023) g_off[N_NODES] = partial[1023];
}

__global__ void fill_kernel(const int* __restrict__ ei) {
    int i = blockIdx.x * blockDim.x + threadIdx.x;
    if (i >= N_EDGES) return;
    int d = ei[N_EDGES + i];
    int slot = atomicAdd(&g_pos[d], 1);
    g_srcs[slot] = ei[i];
}

// ---------------- small dense helpers ----------------------------------------
__global__ void compute_v_kernel(const float* __restrict__ W_src,
                                 const float* __restrict__ att_src,
                                 const float* __restrict__ W_dst,
                                 const float* __restrict__ att_dst,
                                 int Cin, int Cout, int layer) {
    int k = threadIdx.x;
    if (k >= Cin) return;
    float* gv = layer ? g_v2 : g_v1;
    const float* W   = blockIdx.x ? W_dst   : W_src;
    const float* att = blockIdx.x ? att_dst : att_src;
    float s = 0.0f;
    for (int j = 0; j < Cout; j++) s += W[(size_t)k * Cout + j] * att[j];
    gv[blockIdx.x * HID + k] = s;
}

__global__ void compute_a_kernel(const float* __restrict__ Xin, int Cin, int layer) {
    int t = blockIdx.x * blockDim.x + threadIdx.x;
    int node = t >> 5, lane = t & 31;
    if (node >= N_NODES) return;
    const float* X = Xin ? Xin : g_X1;
    const float* gv = layer ? g_v2 : g_v1;
    const float4* Xr = reinterpret_cast<const float4*>(X + (size_t)node * Cin);
    const float4* v1 = reinterpret_cast<const float4*>(gv);
    const float4* v2 = reinterpret_cast<const float4*>(gv + HID);
    float s1 = 0.0f, s2 = 0.0f;
    for (int c = lane; c < Cin / 4; c += 32) {
        float4 xv = Xr[c];
        float4 a = v1[c], b = v2[c];
        s1 += xv.x * a.x + xv.y * a.y + xv.z * a.z + xv.w * a.w;
        s2 += xv.x * b.x + xv.y * b.y + xv.z * b.z + xv.w * b.w;
    }
    #pragma unroll
    for (int o = 16; o; o >>= 1) {
        s1 += __shfl_down_sync(0xFFFFFFFFu, s1, o);
        s2 += __shfl_down_sync(0xFFFFFFFFu, s2, o);
    }
    if (lane == 0) { g_asrc[node] = s1; g_adst[node] = s2; }
}

// W [K=256, Cout] fp32 -> Bh/Bl [Cout][256] bf16 hi/lo (transposed, K-major)
__global__ void convert_W_kernel(const float* __restrict__ W, int Cout, int layer) {
    int idx = blockIdx.x * blockDim.x + threadIdx.x;   // n*256 + k
    if (idx >= 256 * Cout) return;
    __nv_bfloat16* Bh = layer ? g_Bh2 : g_Bh1;
    __nv_bfloat16* Bl = layer ? g_Bl2 : g_Bl1;
    int n = idx >> 8, k = idx & 255;
    float w = W[(size_t)k * Cout + n];
    __nv_bfloat16 wh = __float2bfloat16(w);
    Bh[idx] = wh;
    Bl[idx] = __float2bfloat16(w - __bfloat162float(wh));
}

// ---------------- WMMA bf16x3 GEMM v3.1: race-free double buffer --------------
// 128x128 block tile, 8 warps 4(m)x2(n), warp tile 32x64. K chunks of 32 (8).
// A converted fp32->bf16 hi/lo IN-KERNEL (regs), B via cp.async from pre-split.
// D = Ah*Bh + Ah*Bl + Al*Bh  (fp32 accumulate).
#define PITCH2 40                                 // bf16 elems; 80B row pitch
#define MAT2 (128 * PITCH2)                       // elems per matrix per stage
#define STAGE_EL (4 * MAT2)                       // Ah, Al, Bh, Bl
#define SMB (2 * STAGE_EL * 2)                    // 81920 bytes

__global__ __launch_bounds__(256)
void wmma_gemm_kernel(const float* __restrict__ Ain, int M, int Ntot, int layer) {
    extern __shared__ __nv_bfloat16 sm[];
    const float* A = Ain ? Ain : g_X1;
    float* Hout = layer ? g_H2 : g_H;
    const __nv_bfloat16* BhG16 = layer ? g_Bh2 : g_Bh1;
    const __nv_bfloat16* BlG16 = layer ? g_Bl2 : g_Bl1;
    const int tid  = threadIdx.x;
    const int wid  = tid >> 5;
    const int wm   = wid & 3;
    const int wn   = wid >> 2;
    const int row0 = blockIdx.x * 128;
    const int col0 = blockIdx.y * 128;
    const uint32_t smb = (uint32_t)__cvta_generic_to_shared(sm);

    wmma::fragment<wmma::accumulator, 16, 16, 16, float> acc[2][4];
    #pragma unroll
    for (int i = 0; i < 2; i++)
        #pragma unroll
        for (int j = 0; j < 4; j++) wmma::fill_fragment(acc[i][j], 0.0f);

    auto issueB = [&](int c, int s) {
        const int k0 = c * 32;
        const uint32_t so = (uint32_t)s * STAGE_EL * 2;
        #pragma unroll
        for (int t = 0; t < 4; t++) {
            const int mat = t >> 1;                // 0=Bh, 1=Bl
            int id = ((t & 1) << 8) + tid;         // 0..511
            int r = id >> 2, q = id & 3;
            const __nv_bfloat16* gp = mat ? BlG16 : BhG16;
            const void* src = gp + (size_t)(col0 + r) * 256 + k0 + q * 8;
            uint32_t dst = smb + so + (uint32_t)((2 + mat) * MAT2 + r * PITCH2 + q * 8) * 2;
            cp_async16(dst, src);
        }
        asm volatile("cp.async.commit_group;" ::: "memory");
    };

    float4 ra[4];
    auto loadA = [&](int c) {
        const int k0 = c * 32;
        #pragma unroll
        for (int i = 0; i < 4; i++) {
            int idx = tid + (i << 8);
            int r = idx >> 3, q = idx & 7;
            int grow = row0 + r;
            ra[i] = (grow < M)
                ? *reinterpret_cast<const float4*>(&A[(size_t)grow * 256 + k0 + q * 4])
                : make_float4(0.f, 0.f, 0.f, 0.f);
        }
    };
    auto stsA = [&](int s) {
        __nv_bfloat16* Ah = sm + s * STAGE_EL;
        __nv_bfloat16* Al = Ah + MAT2;
        #pragma unroll
        for (int i = 0; i < 4; i++) {
            int idx = tid + (i << 8);
            int r = idx >> 3, q = idx & 7;
            float4 v = ra[i];
            __nv_bfloat16 h0 = __float2bfloat16(v.x), h1 = __float2bfloat16(v.y);
            __nv_bfloat16 h2 = __float2bfloat16(v.z), h3 = __float2bfloat16(v.w);
            __nv_bfloat16 hi[4] = { h0, h1, h2, h3 };
            __nv_bfloat16 lo[4] = {
                __float2bfloat16(v.x - __bfloat162float(h0)),
                __float2bfloat16(v.y - __bfloat162float(h1)),
                __float2bfloat16(v.z - __bfloat162float(h2)),
                __float2bfloat16(v.w - __bfloat162float(h3)) };
            *reinterpret_cast<uint2*>(&Ah[r * PITCH2 + q * 4]) = *reinterpret_cast<uint2*>(hi);
            *reinterpret_cast<uint2*>(&Al[r * PITCH2 + q * 4]) = *reinterpret_cast<uint2*>(lo);
        }
    };

    issueB(0, 0);
    loadA(0);
    for (int c = 0; c < 8; c++) {
        const int s = c & 1;
        stsA(s);                                   // regs(c) -> smem stage s
        if (c < 7) {
            issueB(c + 1, s ^ 1);
            asm volatile("cp.async.wait_group 1;" ::: "memory");   // B(c) done
        } else {
            asm volatile("cp.async.wait_group 0;" ::: "memory");
        }
        __syncthreads();                           // stage s fully staged
        if (c < 7) loadA(c + 1);                   // LDG latency overlaps MMA

        const __nv_bfloat16* Ah = sm + s * STAGE_EL;
        const __nv_bfloat16* Al = Ah + MAT2;
        const __nv_bfloat16* Bh = Al + MAT2;
        const __nv_bfloat16* Bl = Bh + MAT2;
        #pragma unroll
        for (int kk = 0; kk < 2; kk++) {
            const int ks = kk * 16;
            wmma::fragment<wmma::matrix_a, 16, 16, 16, __nv_bfloat16, wmma::row_major> ah[2], al[2];
            #pragma unroll
            for (int i = 0; i < 2; i++) {
                wmma::load_matrix_sync(ah[i], &Ah[(wm * 32 + i * 16) * PITCH2 + ks], PITCH2);
                wmma::load_matrix_sync(al[i], &Al[(wm * 32 + i * 16) * PITCH2 + ks], PITCH2);
            }
            #pragma unroll
            for (int j = 0; j < 4; j++) {
                wmma::fragment<wmma::matrix_b, 16, 16, 16, __nv_bfloat16, wmma::col_major> bh, bl;
                wmma::load_matrix_sync(bh, &Bh[(wn * 64 + j * 16) * PITCH2 + ks], PITCH2);
                wmma::load_matrix_sync(bl, &Bl[(wn * 64 + j * 16) * PITCH2 + ks], PITCH2);
                #pragma unroll
                for (int i = 0; i < 2; i++) {
                    wmma::mma_sync(acc[i][j], ah[i], bh, acc[i][j]);
                    wmma::mma_sync(acc[i][j], ah[i], bl, acc[i][j]);
                    wmma::mma_sync(acc[i][j], al[i], bh, acc[i][j]);
                }
            }
        }
        // RACE FIX: next iteration's issueB writes stage s^1's B region, which
        // slower warps may still be reading in THIS iteration's MMA.
        __syncthreads();
    }

    #pragma unroll
    for (int i = 0; i < 2; i++) {
        int grow = row0 + wm * 32 + i * 16;
        #pragma unroll
        for (int j = 0; j < 4; j++) {
            float* op = &Hout[(size_t)grow * Ntot + col0 + wn * 64 + j * 16];
            wmma::store_matrix_sync(op, acc[i][j], Ntot, wmma::mem_row_major);
        }
    }
}

// ---------------- edge softmax: one gather pass, online max/sum --------------
__global__ void softmax_kernel() {
    int node = (blockIdx.x * blockDim.x + threadIdx.x) >> 5;
    int lane = threadIdx.x & 31;
    if (node >= N_NODES) return;
    const int beg = g_off[node];
    const int end = g_off[node + 1];
    const float adst = g_adst[node];

    float m = -__int_as_float(0x7F800000);   // -inf
    float s = 0.0f;
    for (int j = beg + lane; j < end; j += 32) {
        float e = leaky(g_asrc[g_srcs[j]] + adst);
        g_e[j] = e;
        if (e > m) { s *= __expf(m - e); m = e; }
        s += __expf(e - m);
    }
    float M = m;
    #pragma unroll
    for (int o = 16; o; o >>= 1) M = fmaxf(M, __shfl_xor_sync(0xFFFFFFFFu, M, o));
    float sl = (s > 0.0f) ? s * __expf(m - M) : 0.0f;
    #pragma unroll
    for (int o = 16; o; o >>= 1) sl += __shfl_xor_sync(0xFFFFFFFFu, sl, o);
    if (lane == 0) {
        g_max[node] = (M == -__int_as_float(0x7F800000)) ? 0.0f : M;
        g_sum[node] = 1.0f / (sl + 1e-16f);
    }
}

// ---------------- aggregation: gather-accumulate only ------------------------
// WPN warps per node, each owns a 128-float slice. outp==nullptr -> g_X1.
// C==256 gathers layer-1 g_H; C==128 gathers layer-2 g_H2.
template <int C, bool RELU, int WPN>
__global__ void agg_kernel(float* __restrict__ outp, const float* __restrict__ bias) {
    int gw   = (blockIdx.x * blockDim.x + threadIdx.x) >> 5;
    int lane = threadIdx.x & 31;
    int node = gw / WPN;
    int part = gw % WPN;
    if (node >= N_NODES) return;
    float* out = outp ? outp : g_X1;
    const float* H = (C == 256) ? g_H : g_H2;
    const int beg = g_off[node];
    const int end = g_off[node + 1];
    const float m   = g_max[node];
    const float inv = g_sum[node];

    const int fo = part * 32;
    float4 acc = make_float4(0.f, 0.f, 0.f, 0.f);
    for (int j = beg; j < end; j++) {
        int src = g_srcs[j];                       // warp-broadcast
        float alpha = __expf(g_e[j] - m) * inv;    // broadcast load + MUFU
        float4 v = reinterpret_cast<const float4*>(H + (size_t)src * C)[fo + lane];
        acc.x += alpha * v.x; acc.y += alpha * v.y;
        acc.z += alpha * v.z; acc.w += alpha * v.w;
    }

    float4 b0 = reinterpret_cast<const float4*>(bias)[fo + lane];
    acc.x += b0.x; acc.y += b0.y; acc.z += b0.z; acc.w += b0.w;
    if (RELU) {
        acc.x = fmaxf(acc.x, 0.f); acc.y = fmaxf(acc.y, 0.f);
        acc.z = fmaxf(acc.z, 0.f); acc.w = fmaxf(acc.w, 0.f);
    }
    reinterpret_cast<float4*>(out + (size_t)node * C)[fo + lane] = acc;
}

// ---------------- launch ----------------------------------------------------
// Submission order note: ncu profiles the 6th submitted kernel (-s 5 -c 1).
// Launches are ordered so wmma_gemm_kernel (layer 1) is submission #6 —
// dependencies are carried by streams/events, so this reorder is semantically
// neutral but finally gets the dominant kernel profiled.
extern "C" void kernel_launch(void* const* d_in, const int* in_sizes, int n_in,
                              void* d_out, int out_size) {
    const float* x        = (const float*)d_in[0];
    const int*   ei       = (const int*)d_in[1];   // int32 (JAX x64 disabled)
    const float* W1_src   = (const float*)d_in[2];
    const float* W1_dst   = (const float*)d_in[3];
    const float* att1_src = (const float*)d_in[4];
    const float* att1_dst = (const float*)d_in[5];
    const float* b1       = (const float*)d_in[6];
    const float* W2_src   = (const float*)d_in[7];
    const float* W2_dst   = (const float*)d_in[8];
    const float* att2_src = (const float*)d_in[9];
    const float* att2_dst = (const float*)d_in[10];
    const float* b2       = (const float*)d_in[11];
    float* out = (float*)d_out;

    static cudaStream_t s2 = nullptr;
    static cudaEvent_t evFork, evW2, evS1, evAgg1, evS2;
    if (!s2) {
        cudaStreamCreateWithFlags(&s2, cudaStreamNonBlocking);
        cudaEventCreateWithFlags(&evFork, cudaEventDisableTiming);
        cudaEventCreateWithFlags(&evW2,   cudaEventDisableTiming);
        cudaEventCreateWithFlags(&evS1,   cudaEventDisableTiming);
        cudaEventCreateWithFlags(&evAgg1, cudaEventDisableTiming);
        cudaEventCreateWithFlags(&evS2,   cudaEventDisableTiming);
        cudaFuncSetAttribute(wmma_gemm_kernel,
                             cudaFuncAttributeMaxDynamicSharedMemorySize, SMB);
    }

    const int nodeBlocks  = (N_NODES + 255) / 256;
    const int edgeBlocks  = (N_EDGES + 255) / 256;
    const int warpNodeBlk = (N_NODES * 32 + 255) / 256;
    const int gemmRows    = (N_NODES + 127) / 128;   // 391

    // ---- fork side stream off the capture/main stream ----
    cudaEventRecord(evFork, 0);
    cudaStreamWaitEvent(s2, evFork, 0);

    // Submissions #1-#5 (mixed streams; chosen so #6 is GEMM1)
    convert_W_kernel<<<(256 * OUTC + 255) / 256, 256, 0, s2>>>(W2_src, OUTC, 1);  // #1
    compute_v_kernel<<<2, HID, 0, s2>>>(W2_src, att2_src, W2_dst, att2_dst,
                                        HID, OUTC, 1);                            // #2
    cudaEventRecord(evW2, s2);                       // W2 bf16 + v2 ready
    convert_W_kernel<<<(256 * HID + 255) / 256, 256>>>(W1_src, HID, 0);           // #3 (main)
    compute_v_kernel<<<2, HID, 0, s2>>>(W1_src, att1_src, W1_dst, att1_dst,
                                        HID, HID, 0);                             // #4
    zero_deg_kernel<<<nodeBlocks, 256, 0, s2>>>();                                // #5

    // #6: the dominant kernel — layer-1 GEMM (main stream; after convW1)
    wmma_gemm_kernel<<<dim3(gemmRows, HID / 128), 256, SMB>>>(x, N_NODES, HID, 0);

    // rest of s2 prep (runs concurrently with GEMM1)
    hist_kernel<<<edgeBlocks, 256, 0, s2>>>(ei);
    scan_kernel<<<1, 1024, 0, s2>>>();
    fill_kernel<<<edgeBlocks, 256, 0, s2>>>(ei);
    compute_a_kernel<<<warpNodeBlk, 256, 0, s2>>>(x, HID, 0);
    softmax_kernel<<<warpNodeBlk, 256, 0, s2>>>();
    cudaEventRecord(evS1, s2);                       // softmax1 done

    // main: aggregation 1
    cudaStreamWaitEvent(0, evS1, 0);
    agg_kernel<HID, true, 2><<<(N_NODES * 2 * 32 + 255) / 256, 256>>>(nullptr, b1);
    cudaEventRecord(evAgg1, 0);                      // g_X1 ready

    // s2: layer-2 attention prep (needs g_X1), overlaps GEMM2
    cudaStreamWaitEvent(s2, evAgg1, 0);
    compute_a_kernel<<<warpNodeBlk, 256, 0, s2>>>(nullptr, HID, 1);
    softmax_kernel<<<warpNodeBlk, 256, 0, s2>>>();
    cudaEventRecord(evS2, s2);                       // softmax2 done

    // main: GEMM2 (needs g_X1 same-stream + W2 bf16 from s2) + final agg
    cudaStreamWaitEvent(0, evW2, 0);
    wmma_gemm_kernel<<<dim3(gemmRows, OUTC / 128), 256, SMB>>>(nullptr, N_NODES, OUTC, 1);
    cudaStreamWaitEvent(0, evS2, 0);
    agg_kernel<OUTC, false, 1><<<warpNodeBlk, 256>>>(out, b2);
}

// round 16
// speedup vs baseline: 1.1255x; 1.1255x over previous
#include <cuda_runtime.h>
#include <cuda_bf16.h>
#include <mma.h>
#include <cstdint>

using namespace nvcuda;

#define N_NODES 50000
#define N_PAD   50048            // padded rows so full-tile stores stay in-bounds
#define N_EDGES 800000
#define HID 256
#define OUTC 128
#define NEG_SLOPE 0.2f

// ---------------- scratch (device globals; no allocations allowed) ----------
__device__ float g_H[(size_t)N_PAD * HID];      // layer-1 GEMM output
__device__ float g_H2[(size_t)N_PAD * OUTC];    // layer-2 GEMM output
__device__ float g_X1[(size_t)N_PAD * HID];     // layer-1 output
__device__ float g_asrc[N_NODES];
__device__ float g_adst[N_NODES];
__device__ float g_max[N_NODES];
__device__ float g_sum[N_NODES];                // holds 1/(s+eps)
__device__ float g_e[N_EDGES];                  // per-edge logits (CSR order)
__device__ float g_v1[2 * HID];                 // layer-1 v_src | v_dst
__device__ float g_v2[2 * HID];                 // layer-2 v_src | v_dst
__device__ __nv_bfloat16 g_Bh1[256 * 256];      // W1^T hi (bf16, [N][K] K-major)
__device__ __nv_bfloat16 g_Bl1[256 * 256];      // W1^T lo
__device__ __nv_bfloat16 g_Bh2[256 * 256];      // W2^T hi
__device__ __nv_bfloat16 g_Bl2[256 * 256];      // W2^T lo
// CSR (built once per launch; shared by both layers)
__device__ int g_deg[N_NODES];
__device__ int g_off[N_NODES + 1];
__device__ int g_pos[N_NODES];
__device__ int g_srcs[N_EDGES];                 // src node per dst-sorted slot

__device__ __forceinline__ float leaky(float e) {
    return (e > 0.0f) ? e : NEG_SLOPE * e;
}

__device__ __forceinline__ void cp_async16(uint32_t dst_smem, const void* src) {
    asm volatile("cp.async.cg.shared.global [%0], [%1], 16;"
                 :: "r"(dst_smem), "l"(src));
}

// ---------------- CSR build --------------------------------------------------
__global__ void zero_deg_kernel() {
    int i = blockIdx.x * blockDim.x + threadIdx.x;
    if (i < N_NODES) g_deg[i] = 0;
}

__global__ void hist_kernel(const int* __restrict__ ei) {
    int i = blockIdx.x * blockDim.x + threadIdx.x;
    if (i >= N_EDGES) return;
    atomicAdd(&g_deg[ei[N_EDGES + i]], 1);
}

__global__ void scan_kernel() {
    __shared__ int partial[1024];
    const int t = threadIdx.x;
    const int CH = (N_NODES + 1023) / 1024;
    int b = t * CH;
    int e = b + CH; if (e > N_NODES) e = N_NODES;
    int s = 0;
    for (int i = b; i < e; i++) s += g_deg[i];
    partial[t] = s;
    __syncthreads();
    for (int off = 1; off < 1024; off <<= 1) {
        int v = (t >= off) ? partial[t - off] : 0;
        __syncthreads();
        partial[t] += v;
        __syncthreads();
    }
    int run = (t > 0) ? partial[t - 1] : 0;
    for (int i = b; i < e; i++) {
        int d = g_deg[i];
        g_off[i] = run;
        g_pos[i] = run;
        run += d;
    }
    if (t == 1023) g_off[N_NODES] = partial[1023];
}

__global__ void fill_kernel(const int* __restrict__ ei) {
    int i = blockIdx.x * blockDim.x + threadIdx.x;
    if (i >= N_EDGES) return;
    int d = ei[N_EDGES + i];
    int slot = atomicAdd(&g_pos[d], 1);
    g_srcs[slot] = ei[i];
}

// ---------------- small dense helpers ----------------------------------------
// v = W @ att, warp-parallel: one warp per (which, k). 512 warps total.
// Coalesced lane-strided reduction (was: 1 thread/k serial loop = 37.7us).
__global__ void compute_v_kernel(const float* __restrict__ W_src,
                                 const float* __restrict__ att_src,
                                 const float* __restrict__ W_dst,
                                 const float* __restrict__ att_dst,
                                 int Cin, int Cout, int layer) {
    int gw   = (blockIdx.x * blockDim.x + threadIdx.x) >> 5;
    int lane = threadIdx.x & 31;
    int which = gw >> 8;            // 0 = src, 1 = dst
    int k     = gw & 255;
    if (which > 1 || k >= Cin) return;
    float* gv = layer ? g_v2 : g_v1;
    const float* W   = which ? W_dst   : W_src;
    const float* att = which ? att_dst : att_src;
    float s = 0.0f;
    for (int j = lane; j < Cout; j += 32)
        s += W[(size_t)k * Cout + j] * att[j];
    #pragma unroll
    for (int o = 16; o; o >>= 1) s += __shfl_down_sync(0xFFFFFFFFu, s, o);
    if (lane == 0) gv[which * HID + k] = s;
}

__global__ void compute_a_kernel(const float* __restrict__ Xin, int Cin, int layer) {
    int t = blockIdx.x * blockDim.x + threadIdx.x;
    int node = t >> 5, lane = t & 31;
    if (node >= N_NODES) return;
    const float* X = Xin ? Xin : g_X1;
    const float* gv = layer ? g_v2 : g_v1;
    const float4* Xr = reinterpret_cast<const float4*>(X + (size_t)node * Cin);
    const float4* v1 = reinterpret_cast<const float4*>(gv);
    const float4* v2 = reinterpret_cast<const float4*>(gv + HID);
    float s1 = 0.0f, s2 = 0.0f;
    for (int c = lane; c < Cin / 4; c += 32) {
        float4 xv = Xr[c];
        float4 a = v1[c], b = v2[c];
        s1 += xv.x * a.x + xv.y * a.y + xv.z * a.z + xv.w * a.w;
        s2 += xv.x * b.x + xv.y * b.y + xv.z * b.z + xv.w * b.w;
    }
    #pragma unroll
    for (int o = 16; o; o >>= 1) {
        s1 += __shfl_down_sync(0xFFFFFFFFu, s1, o);
        s2 += __shfl_down_sync(0xFFFFFFFFu, s2, o);
    }
    if (lane == 0) { g_asrc[node] = s1; g_adst[node] = s2; }
}

// W [K=256, Cout] fp32 -> Bh/Bl [Cout][256] bf16 hi/lo (transposed, K-major)
__global__ void convert_W_kernel(const float* __restrict__ W, int Cout, int layer) {
    int idx = blockIdx.x * blockDim.x + threadIdx.x;   // n*256 + k
    if (idx >= 256 * Cout) return;
    __nv_bfloat16* Bh = layer ? g_Bh2 : g_Bh1;
    __nv_bfloat16* Bl = layer ? g_Bl2 : g_Bl1;
    int n = idx >> 8, k = idx & 255;
    float w = W[(size_t)k * Cout + n];
    __nv_bfloat16 wh = __float2bfloat16(w);
    Bh[idx] = wh;
    Bl[idx] = __float2bfloat16(w - __bfloat162float(wh));
}

// ---------------- WMMA bf16x3 GEMM v3.1: race-free double buffer --------------
// 128x128 block tile, 8 warps 4(m)x2(n), warp tile 32x64. K chunks of 32 (8).
// A converted fp32->bf16 hi/lo IN-KERNEL (regs), B via cp.async from pre-split.
// D = Ah*Bh + Ah*Bl + Al*Bh  (fp32 accumulate).
#define PITCH2 40                                 // bf16 elems; 80B row pitch
#define MAT2 (128 * PITCH2)                       // elems per matrix per stage
#define STAGE_EL (4 * MAT2)                       // Ah, Al, Bh, Bl
#define SMB (2 * STAGE_EL * 2)                    // 81920 bytes

__global__ __launch_bounds__(256)
void wmma_gemm_kernel(const float* __restrict__ Ain, int M, int Ntot, int layer) {
    extern __shared__ __nv_bfloat16 sm[];
    const float* A = Ain ? Ain : g_X1;
    float* Hout = layer ? g_H2 : g_H;
    const __nv_bfloat16* BhG16 = layer ? g_Bh2 : g_Bh1;
    const __nv_bfloat16* BlG16 = layer ? g_Bl2 : g_Bl1;
    const int tid  = threadIdx.x;
    const int wid  = tid >> 5;
    const int wm   = wid & 3;
    const int wn   = wid >> 2;
    const int row0 = blockIdx.x * 128;
    const int col0 = blockIdx.y * 128;
    const uint32_t smb = (uint32_t)__cvta_generic_to_shared(sm);

    wmma::fragment<wmma::accumulator, 16, 16, 16, float> acc[2][4];
    #pragma unroll
    for (int i = 0; i < 2; i++)
        #pragma unroll
        for (int j = 0; j < 4; j++) wmma::fill_fragment(acc[i][j], 0.0f);

    auto issueB = [&](int c, int s) {
        const int k0 = c * 32;
        const uint32_t so = (uint32_t)s * STAGE_EL * 2;
        #pragma unroll
        for (int t = 0; t < 4; t++) {
            const int mat = t >> 1;                // 0=Bh, 1=Bl
            int id = ((t & 1) << 8) + tid;         // 0..511
            int r = id >> 2, q = id & 3;
            const __nv_bfloat16* gp = mat ? BlG16 : BhG16;
            const void* src = gp + (size_t)(col0 + r) * 256 + k0 + q * 8;
            uint32_t dst = smb + so + (uint32_t)((2 + mat) * MAT2 + r * PITCH2 + q * 8) * 2;
            cp_async16(dst, src);
        }
        asm volatile("cp.async.commit_group;" ::: "memory");
    };

    float4 ra[4];
    auto loadA = [&](int c) {
        const int k0 = c * 32;
        #pragma unroll
        for (int i = 0; i < 4; i++) {
            int idx = tid + (i << 8);
            int r = idx >> 3, q = idx & 7;
            int grow = row0 + r;
            ra[i] = (grow < M)
                ? *reinterpret_cast<const float4*>(&A[(size_t)grow * 256 + k0 + q * 4])
                : make_float4(0.f, 0.f, 0.f, 0.f);
        }
    };
    auto stsA = [&](int s) {
        __nv_bfloat16* Ah = sm + s * STAGE_EL;
        __nv_bfloat16* Al = Ah + MAT2;
        #pragma unroll
        for (int i = 0; i < 4; i++) {
            int idx = tid + (i << 8);
            int r = idx >> 3, q = idx & 7;
            float4 v = ra[i];
            __nv_bfloat16 h0 = __float2bfloat16(v.x), h1 = __float2bfloat16(v.y);
            __nv_bfloat16 h2 = __float2bfloat16(v.z), h3 = __float2bfloat16(v.w);
            __nv_bfloat16 hi[4] = { h0, h1, h2, h3 };
            __nv_bfloat16 lo[4] = {
                __float2bfloat16(v.x - __bfloat162float(h0)),
                __float2bfloat16(v.y - __bfloat162float(h1)),
                __float2bfloat16(v.z - __bfloat162float(h2)),
                __float2bfloat16(v.w - __bfloat162float(h3)) };
            *reinterpret_cast<uint2*>(&Ah[r * PITCH2 + q * 4]) = *reinterpret_cast<uint2*>(hi);
            *reinterpret_cast<uint2*>(&Al[r * PITCH2 + q * 4]) = *reinterpret_cast<uint2*>(lo);
        }
    };

    issueB(0, 0);
    loadA(0);
    for (int c = 0; c < 8; c++) {
        const int s = c & 1;
        stsA(s);                                   // regs(c) -> smem stage s
        if (c < 7) {
            issueB(c + 1, s ^ 1);
            asm volatile("cp.async.wait_group 1;" ::: "memory");   // B(c) done
        } else {
            asm volatile("cp.async.wait_group 0;" ::: "memory");
        }
        __syncthreads();                           // stage s fully staged
        if (c < 7) loadA(c + 1);                   // LDG latency overlaps MMA

        const __nv_bfloat16* Ah = sm + s * STAGE_EL;
        const __nv_bfloat16* Al = Ah + MAT2;
        const __nv_bfloat16* Bh = Al + MAT2;
        const __nv_bfloat16* Bl = Bh + MAT2;
        #pragma unroll
        for (int kk = 0; kk < 2; kk++) {
            const int ks = kk * 16;
            wmma::fragment<wmma::matrix_a, 16, 16, 16, __nv_bfloat16, wmma::row_major> ah[2], al[2];
            #pragma unroll
            for (int i = 0; i < 2; i++) {
                wmma::load_matrix_sync(ah[i], &Ah[(wm * 32 + i * 16) * PITCH2 + ks], PITCH2);
                wmma::load_matrix_sync(al[i], &Al[(wm * 32 + i * 16) * PITCH2 + ks], PITCH2);
            }
            #pragma unroll
            for (int j = 0; j < 4; j++) {
                wmma::fragment<wmma::matrix_b, 16, 16, 16, __nv_bfloat16, wmma::col_major> bh, bl;
                wmma::load_matrix_sync(bh, &Bh[(wn * 64 + j * 16) * PITCH2 + ks], PITCH2);
                wmma::load_matrix_sync(bl, &Bl[(wn * 64 + j * 16) * PITCH2 + ks], PITCH2);
                #pragma unroll
                for (int i = 0; i < 2; i++) {
                    wmma::mma_sync(acc[i][j], ah[i], bh, acc[i][j]);
                    wmma::mma_sync(acc[i][j], ah[i], bl, acc[i][j]);
                    wmma::mma_sync(acc[i][j], al[i], bh, acc[i][j]);
                }
            }
        }
        // RACE FIX: next iteration's issueB writes stage s^1's B region, which
        // slower warps may still be reading in THIS iteration's MMA.
        __syncthreads();
    }

    #pragma unroll
    for (int i = 0; i < 2; i++) {
        int grow = row0 + wm * 32 + i * 16;
        #pragma unroll
        for (int j = 0; j < 4; j++) {
            float* op = &Hout[(size_t)grow * Ntot + col0 + wn * 64 + j * 16];
            wmma::store_matrix_sync(op, acc[i][j], Ntot, wmma::mem_row_major);
        }
    }
}

// ---------------- edge softmax: one gather pass, online max/sum --------------
__global__ void softmax_kernel() {
    int node = (blockIdx.x * blockDim.x + threadIdx.x) >> 5;
    int lane = threadIdx.x & 31;
    if (node >= N_NODES) return;
    const int beg = g_off[node];
    const int end = g_off[node + 1];
    const float adst = g_adst[node];

    float m = -__int_as_float(0x7F800000);   // -inf
    float s = 0.0f;
    for (int j = beg + lane; j < end; j += 32) {
        float e = leaky(g_asrc[g_srcs[j]] + adst);
        g_e[j] = e;
        if (e > m) { s *= __expf(m - e); m = e; }
        s += __expf(e - m);
    }
    float M = m;
    #pragma unroll
    for (int o = 16; o; o >>= 1) M = fmaxf(M, __shfl_xor_sync(0xFFFFFFFFu, M, o));
    float sl = (s > 0.0f) ? s * __expf(m - M) : 0.0f;
    #pragma unroll
    for (int o = 16; o; o >>= 1) sl += __shfl_xor_sync(0xFFFFFFFFu, sl, o);
    if (lane == 0) {
        g_max[node] = (M == -__int_as_float(0x7F800000)) ? 0.0f : M;
        g_sum[node] = 1.0f / (sl + 1e-16f);
    }
}

// ---------------- aggregation: gather-accumulate only ------------------------
// WPN warps per node, each owns a 128-float slice. outp==nullptr -> g_X1.
// C==256 gathers layer-1 g_H; C==128 gathers layer-2 g_H2.
template <int C, bool RELU, int WPN>
__global__ void agg_kernel(float* __restrict__ outp, const float* __restrict__ bias) {
    int gw   = (blockIdx.x * blockDim.x + threadIdx.x) >> 5;
    int lane = threadIdx.x & 31;
    int node = gw / WPN;
    int part = gw % WPN;
    if (node >= N_NODES) return;
    float* out = outp ? outp : g_X1;
    const float* H = (C == 256) ? g_H : g_H2;
    const int beg = g_off[node];
    const int end = g_off[node + 1];
    const float m   = g_max[node];
    const float inv = g_sum[node];

    const int fo = part * 32;
    float4 acc = make_float4(0.f, 0.f, 0.f, 0.f);
    for (int j = beg; j < end; j++) {
        int src = g_srcs[j];                       // warp-broadcast
        float alpha = __expf(g_e[j] - m) * inv;    // broadcast load + MUFU
        float4 v = reinterpret_cast<const float4*>(H + (size_t)src * C)[fo + lane];
        acc.x += alpha * v.x; acc.y += alpha * v.y;
        acc.z += alpha * v.z; acc.w += alpha * v.w;
    }

    float4 b0 = reinterpret_cast<const float4*>(bias)[fo + lane];
    acc.x += b0.x; acc.y += b0.y; acc.z += b0.z; acc.w += b0.w;
    if (RELU) {
        acc.x = fmaxf(acc.x, 0.f); acc.y = fmaxf(acc.y, 0.f);
        acc.z = fmaxf(acc.z, 0.f); acc.w = fmaxf(acc.w, 0.f);
    }
    reinterpret_cast<float4*>(out + (size_t)node * C)[fo + lane] = acc;
}

// ---------------- launch ----------------------------------------------------
// Schedule: main = convW1 -> GEMM1 -> agg1 -> GEMM2 -> agg2.
// s2 = CSR build -> softmax1 -> (post agg1) compute_a2 -> softmax2.
// s3 = convW2/compute_v2 + compute_v1/compute_a1 (parallel with CSR on s2).
extern "C" void kernel_launch(void* const* d_in, const int* in_sizes, int n_in,
                              void* d_out, int out_size) {
    const float* x        = (const float*)d_in[0];
    const int*   ei       = (const int*)d_in[1];   // int32 (JAX x64 disabled)
    const float* W1_src   = (const float*)d_in[2];
    const float* W1_dst   = (const float*)d_in[3];
    const float* att1_src = (const float*)d_in[4];
    const float* att1_dst = (const float*)d_in[5];
    const float* b1       = (const float*)d_in[6];
    const float* W2_src   = (const float*)d_in[7];
    const float* W2_dst   = (const float*)d_in[8];
    const float* att2_src = (const float*)d_in[9];
    const float* att2_dst = (const float*)d_in[10];
    const float* b2       = (const float*)d_in[11];
    float* out = (float*)d_out;

    static cudaStream_t s2 = nullptr, s3 = nullptr;
    static cudaEvent_t evFork, evW2, evA1, evS1, evAgg1, evS2;
    if (!s2) {
        cudaStreamCreateWithFlags(&s2, cudaStreamNonBlocking);
        cudaStreamCreateWithFlags(&s3, cudaStreamNonBlocking);
        cudaEventCreateWithFlags(&evFork, cudaEventDisableTiming);
        cudaEventCreateWithFlags(&evW2,   cudaEventDisableTiming);
        cudaEventCreateWithFlags(&evA1,   cudaEventDisableTiming);
        cudaEventCreateWithFlags(&evS1,   cudaEventDisableTiming);
        cudaEventCreateWithFlags(&evAgg1, cudaEventDisableTiming);
        cudaEventCreateWithFlags(&evS2,   cudaEventDisableTiming);
        cudaFuncSetAttribute(wmma_gemm_kernel,
                             cudaFuncAttributeMaxDynamicSharedMemorySize, SMB);
    }

    const int nodeBlocks  = (N_NODES + 255) / 256;
    const int edgeBlocks  = (N_EDGES + 255) / 256;
    const int warpNodeBlk = (N_NODES * 32 + 255) / 256;
    const int vBlocks     = (512 * 32 + 255) / 256;   // 512 warps for compute_v
    const int gemmRows    = (N_NODES + 127) / 128;    // 391

    // ---- fork side streams off the capture/main stream ----
    cudaEventRecord(evFork, 0);
    cudaStreamWaitEvent(s2, evFork, 0);
    cudaStreamWaitEvent(s3, evFork, 0);

    // s3: weight prep for both layers + layer-1 attention dots (|| CSR on s2)
    convert_W_kernel<<<(256 * OUTC + 255) / 256, 256, 0, s3>>>(W2_src, OUTC, 1);
    compute_v_kernel<<<vBlocks, 256, 0, s3>>>(W2_src, att2_src, W2_dst, att2_dst,
                                              HID, OUTC, 1);
    cudaEventRecord(evW2, s3);                       // g_Bh2/g_Bl2 + g_v2 ready
    compute_v_kernel<<<vBlocks, 256, 0, s3>>>(W1_src, att1_src, W1_dst, att1_dst,
                                              HID, HID, 0);
    compute_a_kernel<<<warpNodeBlk, 256, 0, s3>>>(x, HID, 0);
    cudaEventRecord(evA1, s3);                       // g_asrc/g_adst (layer 1)

    // s2: CSR build (parallel with s3 chain and main GEMM1)
    zero_deg_kernel<<<nodeBlocks, 256, 0, s2>>>();
    hist_kernel<<<edgeBlocks, 256, 0, s2>>>(ei);
    scan_kernel<<<1, 1024, 0, s2>>>();
    fill_kernel<<<edgeBlocks, 256, 0, s2>>>(ei);
    cudaStreamWaitEvent(s2, evA1, 0);
    softmax_kernel<<<warpNodeBlk, 256, 0, s2>>>();
    cudaEventRecord(evS1, s2);                       // softmax1 done

    // main: layer-1 GEMM chain
    convert_W_kernel<<<(256 * HID + 255) / 256, 256>>>(W1_src, HID, 0);
    wmma_gemm_kernel<<<dim3(gemmRows, HID / 128), 256, SMB>>>(x, N_NODES, HID, 0);
    cudaStreamWaitEvent(0, evS1, 0);
    agg_kernel<HID, true, 2><<<(N_NODES * 2 * 32 + 255) / 256, 256>>>(nullptr, b1);
    cudaEventRecord(evAgg1, 0);                      // g_X1 ready

    // s2: layer-2 attention prep (needs g_X1 + g_v2), overlaps GEMM2
    cudaStreamWaitEvent(s2, evAgg1, 0);
    cudaStreamWaitEvent(s2, evW2, 0);                // g_v2 from s3
    compute_a_kernel<<<warpNodeBlk, 256, 0, s2>>>(nullptr, HID, 1);
    softmax_kernel<<<warpNodeBlk, 256, 0, s2>>>();
    cudaEventRecord(evS2, s2);                       // softmax2 done

    // main: GEMM2 (needs g_X1 same-stream + W2 bf16 from s3) + final agg
    cudaStreamWaitEvent(0, evW2, 0);
    wmma_gemm_kernel<<<dim3(gemmRows, OUTC / 128), 256, SMB>>>(nullptr, N_NODES, OUTC, 1);
    cudaStreamWaitEvent(0, evS2, 0);
    agg_kernel<OUTC, false, 1><<<warpNodeBlk, 256>>>(out, b2);
}

// round 17
// speedup vs baseline: 1.2306x; 1.0933x over previous
#include <cuda_runtime.h>
#include <cuda_fp16.h>
#include <mma.h>
#include <cstdint>

using namespace nvcuda;

#define N_NODES 50000
#define N_PAD   50048            // padded rows so full-tile stores stay in-bounds
#define N_EDGES 800000
#define HID 256
#define OUTC 128
#define NEG_SLOPE 0.2f

// ---------------- scratch (device globals; no allocations allowed) ----------
__device__ float g_H[(size_t)N_PAD * HID];      // layer-1 GEMM output
__device__ float g_H2[(size_t)N_PAD * OUTC];    // layer-2 GEMM output
__device__ float g_X1[(size_t)N_PAD * HID];     // layer-1 output
__device__ float g_asrc[N_NODES];
__device__ float g_adst[N_NODES];
__device__ float g_max[N_NODES];
__device__ float g_sum[N_NODES];                // holds 1/(s+eps)
__device__ float g_e[N_EDGES];                  // per-edge logits (CSR order)
__device__ float g_v1[2 * HID];                 // layer-1 v_src | v_dst
__device__ float g_v2[2 * HID];                 // layer-2 v_src | v_dst
__device__ __half g_Bh1[256 * 256];             // W1^T hi (fp16, [N][K] K-major)
__device__ __half g_Bl1[256 * 256];             // W1^T lo
__device__ __half g_Bh2[256 * 256];             // W2^T hi
__device__ __half g_Bl2[256 * 256];             // W2^T lo
// CSR (built once per launch; shared by both layers)
__device__ int g_deg[N_NODES];
__device__ int g_off[N_NODES + 1];
__device__ int g_pos[N_NODES];
__device__ int g_srcs[N_EDGES];                 // src node per dst-sorted slot

__device__ __forceinline__ float leaky(float e) {
    return (e > 0.0f) ? e : NEG_SLOPE * e;
}

__device__ __forceinline__ void cp_async16(uint32_t dst_smem, const void* src) {
    asm volatile("cp.async.cg.shared.global [%0], [%1], 16;"
                 :: "r"(dst_smem), "l"(src));
}

// ---------------- CSR build --------------------------------------------------
__global__ void zero_deg_kernel() {
    int i = blockIdx.x * blockDim.x + threadIdx.x;
    if (i < N_NODES) g_deg[i] = 0;
}

__global__ void hist_kernel(const int* __restrict__ ei) {
    int i = blockIdx.x * blockDim.x + threadIdx.x;
    if (i >= N_EDGES) return;
    atomicAdd(&g_deg[ei[N_EDGES + i]], 1);
}

__global__ void scan_kernel() {
    __shared__ int partial[1024];
    const int t = threadIdx.x;
    const int CH = (N_NODES + 1023) / 1024;
    int b = t * CH;
    int e = b + CH; if (e > N_NODES) e = N_NODES;
    int s = 0;
    for (int i = b; i < e; i++) s += g_deg[i];
    partial[t] = s;
    __syncthreads();
    for (int off = 1; off < 1024; off <<= 1) {
        int v = (t >= off) ? partial[t - off] : 0;
        __syncthreads();
        partial[t] += v;
        __syncthreads();
    }
    int run = (t > 0) ? partial[t - 1] : 0;
    for (int i = b; i < e; i++) {
        int d = g_deg[i];
        g_off[i] = run;
        g_pos[i] = run;
        run += d;
    }
    if (t == 1023) g_off[N_NODES] = partial[1023];
}

__global__ void fill_kernel(const int* __restrict__ ei) {
    int i = blockIdx.x * blockDim.x + threadIdx.x;
    if (i >= N_EDGES) return;
    int d = ei[N_EDGES + i];
    int slot = atomicAdd(&g_pos[d], 1);
    g_srcs[slot] = ei[i];
}

// ---------------- small dense helpers ----------------------------------------
// v = W @ att, warp-parallel: one warp per (which, k). 512 warps total.
__global__ void compute_v_kernel(const float* __restrict__ W_src,
                                 const float* __restrict__ att_src,
                                 const float* __restrict__ W_dst,
                                 const float* __restrict__ att_dst,
                                 int Cin, int Cout, int layer) {
    int gw   = (blockIdx.x * blockDim.x + threadIdx.x) >> 5;
    int lane = threadIdx.x & 31;
    int which = gw >> 8;            // 0 = src, 1 = dst
    int k     = gw & 255;
    if (which > 1 || k >= Cin) return;
    float* gv = layer ? g_v2 : g_v1;
    const float* W   = which ? W_dst   : W_src;
    const float* att = which ? att_dst : att_src;
    float s = 0.0f;
    for (int j = lane; j < Cout; j += 32)
        s += W[(size_t)k * Cout + j] * att[j];
    #pragma unroll
    for (int o = 16; o; o >>= 1) s += __shfl_down_sync(0xFFFFFFFFu, s, o);
    if (lane == 0) gv[which * HID + k] = s;
}

__global__ void compute_a_kernel(const float* __restrict__ Xin, int Cin, int layer) {
    int t = blockIdx.x * blockDim.x + threadIdx.x;
    int node = t >> 5, lane = t & 31;
    if (node >= N_NODES) return;
    const float* X = Xin ? Xin : g_X1;
    const float* gv = layer ? g_v2 : g_v1;
    const float4* Xr = reinterpret_cast<const float4*>(X + (size_t)node * Cin);
    const float4* v1 = reinterpret_cast<const float4*>(gv);
    const float4* v2 = reinterpret_cast<const float4*>(gv + HID);
    float s1 = 0.0f, s2 = 0.0f;
    for (int c = lane; c < Cin / 4; c += 32) {
        float4 xv = Xr[c];
        float4 a = v1[c], b = v2[c];
        s1 += xv.x * a.x + xv.y * a.y + xv.z * a.z + xv.w * a.w;
        s2 += xv.x * b.x + xv.y * b.y + xv.z * b.z + xv.w * b.w;
    }
    #pragma unroll
    for (int o = 16; o; o >>= 1) {
        s1 += __shfl_down_sync(0xFFFFFFFFu, s1, o);
        s2 += __shfl_down_sync(0xFFFFFFFFu, s2, o);
    }
    if (lane == 0) { g_asrc[node] = s1; g_adst[node] = s2; }
}

// W [K=256, Cout] fp32 -> Bh/Bl [Cout][256] fp16 hi/lo (transposed, K-major)
__global__ void convert_W_kernel(const float* __restrict__ W, int Cout, int layer) {
    int idx = blockIdx.x * blockDim.x + threadIdx.x;   // n*256 + k
    if (idx >= 256 * Cout) return;
    __half* Bh = layer ? g_Bh2 : g_Bh1;
    __half* Bl = layer ? g_Bl2 : g_Bl1;
    int n = idx >> 8, k = idx & 255;
    float w = W[(size_t)k * Cout + n];
    __half wh = __float2half_rn(w);
    Bh[idx] = wh;
    Bl[idx] = __float2half_rn(w - __half2float(wh));
}

// ---------------- WMMA fp16x2 GEMM: race-free double buffer -------------------
// 128x128 block tile, 8 warps 4(m)x2(n), warp tile 32x64. K chunks of 32 (8).
// A converted fp32->fp16 (hi only) IN-KERNEL; B hi/lo via cp.async (pre-split).
// D = Ah*Bh + Ah*Bl  (fp32 accumulate; dropped Al*B term ~2^-12 relative).
#define PITCH2 40                                 // fp16 elems; 80B row pitch
#define MAT2 (128 * PITCH2)                       // elems per matrix per stage
#define STAGE_EL (3 * MAT2)                       // Ah, Bh, Bl
#define SMB (2 * STAGE_EL * 2)                    // 61440 bytes

__global__ __launch_bounds__(256)
void wmma_gemm_kernel(const float* __restrict__ Ain, int M, int Ntot, int layer) {
    extern __shared__ __half sm[];
    const float* A = Ain ? Ain : g_X1;
    float* Hout = layer ? g_H2 : g_H;
    const __half* BhG16 = layer ? g_Bh2 : g_Bh1;
    const __half* BlG16 = layer ? g_Bl2 : g_Bl1;
    const int tid  = threadIdx.x;
    const int wid  = tid >> 5;
    const int wm   = wid & 3;
    const int wn   = wid >> 2;
    const int row0 = blockIdx.x * 128;
    const int col0 = blockIdx.y * 128;
    const uint32_t smb = (uint32_t)__cvta_generic_to_shared(sm);

    wmma::fragment<wmma::accumulator, 16, 16, 16, float> acc[2][4];
    #pragma unroll
    for (int i = 0; i < 2; i++)
        #pragma unroll
        for (int j = 0; j < 4; j++) wmma::fill_fragment(acc[i][j], 0.0f);

    // B chunk: 128 n-rows x 32 k (64B = 4 x 16B per row) for Bh and Bl
    auto issueB = [&](int c, int s) {
        const int k0 = c * 32;
        const uint32_t so = (uint32_t)s * STAGE_EL * 2;
        #pragma unroll
        for (int t = 0; t < 4; t++) {
            const int mat = t >> 1;                // 0=Bh, 1=Bl
            int id = ((t & 1) << 8) + tid;         // 0..511
            int r = id >> 2, q = id & 3;
            const __half* gp = mat ? BlG16 : BhG16;
            const void* src = gp + (size_t)(col0 + r) * 256 + k0 + q * 8;
            uint32_t dst = smb + so + (uint32_t)((1 + mat) * MAT2 + r * PITCH2 + q * 8) * 2;
            cp_async16(dst, src);
        }
        asm volatile("cp.async.commit_group;" ::: "memory");
    };

    // A chunk: 128 m-rows x 32 k fp32 = 1024 float4, 4 per thread
    float4 ra[4];
    auto loadA = [&](int c) {
        const int k0 = c * 32;
        #pragma unroll
        for (int i = 0; i < 4; i++) {
            int idx = tid + (i << 8);
            int r = idx >> 3, q = idx & 7;
            int grow = row0 + r;
            ra[i] = (grow < M)
                ? *reinterpret_cast<const float4*>(&A[(size_t)grow * 256 + k0 + q * 4])
                : make_float4(0.f, 0.f, 0.f, 0.f);
        }
    };
    auto stsA = [&](int s) {
        __half* Ah = sm + s * STAGE_EL;
        #pragma unroll
        for (int i = 0; i < 4; i++) {
            int idx = tid + (i << 8);
            int r = idx >> 3, q = idx & 7;
            float4 v = ra[i];
            __half hi[4] = { __float2half_rn(v.x), __float2half_rn(v.y),
                             __float2half_rn(v.z), __float2half_rn(v.w) };
            *reinterpret_cast<uint2*>(&Ah[r * PITCH2 + q * 4]) = *reinterpret_cast<uint2*>(hi);
        }
    };

    issueB(0, 0);
    loadA(0);
    for (int c = 0; c < 8; c++) {
        const int s = c & 1;
        stsA(s);                                   // regs(c) -> smem stage s
        if (c < 7) {
            issueB(c + 1, s ^ 1);
            asm volatile("cp.async.wait_group 1;" ::: "memory");   // B(c) done
        } else {
            asm volatile("cp.async.wait_group 0;" ::: "memory");
        }
        __syncthreads();                           // stage s fully staged
        if (c < 7) loadA(c + 1);                   // LDG latency overlaps MMA

        const __half* Ah = sm + s * STAGE_EL;
        const __half* Bh = Ah + MAT2;
        const __half* Bl = Bh + MAT2;
        #pragma unroll
        for (int kk = 0; kk < 2; kk++) {
            const int ks = kk * 16;
            wmma::fragment<wmma::matrix_a, 16, 16, 16, __half, wmma::row_major> ah[2];
            #pragma unroll
            for (int i = 0; i < 2; i++)
                wmma::load_matrix_sync(ah[i], &Ah[(wm * 32 + i * 16) * PITCH2 + ks], PITCH2);
            #pragma unroll
            for (int j = 0; j < 4; j++) {
                wmma::fragment<wmma::matrix_b, 16, 16, 16, __half, wmma::col_major> bh, bl;
                wmma::load_matrix_sync(bh, &Bh[(wn * 64 + j * 16) * PITCH2 + ks], PITCH2);
                wmma::load_matrix_sync(bl, &Bl[(wn * 64 + j * 16) * PITCH2 + ks], PITCH2);
                #pragma unroll
                for (int i = 0; i < 2; i++) {
                    wmma::mma_sync(acc[i][j], ah[i], bh, acc[i][j]);
                    wmma::mma_sync(acc[i][j], ah[i], bl, acc[i][j]);
                }
            }
        }
        // RACE FIX: next iteration's issueB writes stage s^1's B region, which
        // slower warps may still be reading in THIS iteration's MMA.
        __syncthreads();
    }

    #pragma unroll
    for (int i = 0; i < 2; i++) {
        int grow = row0 + wm * 32 + i * 16;
        #pragma unroll
        for (int j = 0; j < 4; j++) {
            float* op = &Hout[(size_t)grow * Ntot + col0 + wn * 64 + j * 16];
            wmma::store_matrix_sync(op, acc[i][j], Ntot, wmma::mem_row_major);
        }
    }
}

// ---------------- edge softmax: one gather pass, online max/sum --------------
__global__ void softmax_kernel() {
    int node = (blockIdx.x * blockDim.x + threadIdx.x) >> 5;
    int lane = threadIdx.x & 31;
    if (node >= N_NODES) return;
    const int beg = g_off[node];
    const int end = g_off[node + 1];
    const float adst = g_adst[node];

    float m = -__int_as_float(0x7F800000);   // -inf
    float s = 0.0f;
    for (int j = beg + lane; j < end; j += 32) {
        float e = leaky(g_asrc[g_srcs[j]] + adst);
        g_e[j] = e;
        if (e > m) { s *= __expf(m - e); m = e; }
        s += __expf(e - m);
    }
    float M = m;
    #pragma unroll
    for (int o = 16; o; o >>= 1) M = fmaxf(M, __shfl_xor_sync(0xFFFFFFFFu, M, o));
    float sl = (s > 0.0f) ? s * __expf(m - M) : 0.0f;
    #pragma unroll
    for (int o = 16; o; o >>= 1) sl += __shfl_xor_sync(0xFFFFFFFFu, sl, o);
    if (lane == 0) {
        g_max[node] = (M == -__int_as_float(0x7F800000)) ? 0.0f : M;
        g_sum[node] = 1.0f / (sl + 1e-16f);
    }
}

// ---------------- aggregation: gather-accumulate only ------------------------
// WPN warps per node, each owns a 128-float slice. outp==nullptr -> g_X1.
// C==256 gathers layer-1 g_H; C==128 gathers layer-2 g_H2.
template <int C, bool RELU, int WPN>
__global__ void agg_kernel(float* __restrict__ outp, const float* __restrict__ bias) {
    int gw   = (blockIdx.x * blockDim.x + threadIdx.x) >> 5;
    int lane = threadIdx.x & 31;
    int node = gw / WPN;
    int part = gw % WPN;
    if (node >= N_NODES) return;
    float* out = outp ? outp : g_X1;
    const float* H = (C == 256) ? g_H : g_H2;
    const int beg = g_off[node];
    const int end = g_off[node + 1];
    const float m   = g_max[node];
    const float inv = g_sum[node];

    const int fo = part * 32;
    float4 acc = make_float4(0.f, 0.f, 0.f, 0.f);
    for (int j = beg; j < end; j++) {
        int src = g_srcs[j];                       // warp-broadcast
        float alpha = __expf(g_e[j] - m) * inv;    // broadcast load + MUFU
        float4 v = reinterpret_cast<const float4*>(H + (size_t)src * C)[fo + lane];
        acc.x += alpha * v.x; acc.y += alpha * v.y;
        acc.z += alpha * v.z; acc.w += alpha * v.w;
    }

    float4 b0 = reinterpret_cast<const float4*>(bias)[fo + lane];
    acc.x += b0.x; acc.y += b0.y; acc.z += b0.z; acc.w += b0.w;
    if (RELU) {
        acc.x = fmaxf(acc.x, 0.f); acc.y = fmaxf(acc.y, 0.f);
        acc.z = fmaxf(acc.z, 0.f); acc.w = fmaxf(acc.w, 0.f);
    }
    reinterpret_cast<float4*>(out + (size_t)node * C)[fo + lane] = acc;
}

// ---------------- launch ----------------------------------------------------
// Schedule: main = convW1 -> GEMM1 -> agg1 -> GEMM2 -> agg2.
// s2 = CSR build -> softmax1 -> (post agg1) compute_a2 -> softmax2.
// s3 = convW2/compute_v2 + compute_v1/compute_a1 (parallel with CSR on s2).
extern "C" void kernel_launch(void* const* d_in, const int* in_sizes, int n_in,
                              void* d_out, int out_size) {
    const float* x        = (const float*)d_in[0];
    const int*   ei       = (const int*)d_in[1];   // int32 (JAX x64 disabled)
    const float* W1_src   = (const float*)d_in[2];
    const float* W1_dst   = (const float*)d_in[3];
    const float* att1_src = (const float*)d_in[4];
    const float* att1_dst = (const float*)d_in[5];
    const float* b1       = (const float*)d_in[6];
    const float* W2_src   = (const float*)d_in[7];
    const float* W2_dst   = (const float*)d_in[8];
    const float* att2_src = (const float*)d_in[9];
    const float* att2_dst = (const float*)d_in[10];
    const float* b2       = (const float*)d_in[11];
    float* out = (float*)d_out;

    static cudaStream_t s2 = nullptr, s3 = nullptr;
    static cudaEvent_t evFork, evW2, evA1, evS1, evAgg1, evS2;
    if (!s2) {
        cudaStreamCreateWithFlags(&s2, cudaStreamNonBlocking);
        cudaStreamCreateWithFlags(&s3, cudaStreamNonBlocking);
        cudaEventCreateWithFlags(&evFork, cudaEventDisableTiming);
        cudaEventCreateWithFlags(&evW2,   cudaEventDisableTiming);
        cudaEventCreateWithFlags(&evA1,   cudaEventDisableTiming);
        cudaEventCreateWithFlags(&evS1,   cudaEventDisableTiming);
        cudaEventCreateWithFlags(&evAgg1, cudaEventDisableTiming);
        cudaEventCreateWithFlags(&evS2,   cudaEventDisableTiming);
        cudaFuncSetAttribute(wmma_gemm_kernel,
                             cudaFuncAttributeMaxDynamicSharedMemorySize, SMB);
    }

    const int nodeBlocks  = (N_NODES + 255) / 256;
    const int edgeBlocks  = (N_EDGES + 255) / 256;
    const int warpNodeBlk = (N_NODES * 32 + 255) / 256;
    const int vBlocks     = (512 * 32 + 255) / 256;   // 512 warps for compute_v
    const int gemmRows    = (N_NODES + 127) / 128;    // 391

    // ---- fork side streams off the capture/main stream ----
    cudaEventRecord(evFork, 0);
    cudaStreamWaitEvent(s2, evFork, 0);
    cudaStreamWaitEvent(s3, evFork, 0);

    // s3: weight prep for both layers + layer-1 attention dots (|| CSR on s2)
    convert_W_kernel<<<(256 * OUTC + 255) / 256, 256, 0, s3>>>(W2_src, OUTC, 1);
    compute_v_kernel<<<vBlocks, 256, 0, s3>>>(W2_src, att2_src, W2_dst, att2_dst,
                                              HID, OUTC, 1);
    cudaEventRecord(evW2, s3);                       // g_Bh2/g_Bl2 + g_v2 ready
    compute_v_kernel<<<vBlocks, 256, 0, s3>>>(W1_src, att1_src, W1_dst, att1_dst,
                                              HID, HID, 0);
    compute_a_kernel<<<warpNodeBlk, 256, 0, s3>>>(x, HID, 0);
    cudaEventRecord(evA1, s3);                       // g_asrc/g_adst (layer 1)

    // s2: CSR build (parallel with s3 chain and main GEMM1)
    zero_deg_kernel<<<nodeBlocks, 256, 0, s2>>>();
    hist_kernel<<<edgeBlocks, 256, 0, s2>>>(ei);
    scan_kernel<<<1, 1024, 0, s2>>>();
    fill_kernel<<<edgeBlocks, 256, 0, s2>>>(ei);
    cudaStreamWaitEvent(s2, evA1, 0);
    softmax_kernel<<<warpNodeBlk, 256, 0, s2>>>();
    cudaEventRecord(evS1, s2);                       // softmax1 done

    // main: layer-1 GEMM chain
    convert_W_kernel<<<(256 * HID + 255) / 256, 256>>>(W1_src, HID, 0);
    wmma_gemm_kernel<<<dim3(gemmRows, HID / 128), 256, SMB>>>(x, N_NODES, HID, 0);
    cudaStreamWaitEvent(0, evS1, 0);
    agg_kernel<HID, true, 2><<<(N_NODES * 2 * 32 + 255) / 256, 256>>>(nullptr, b1);
    cudaEventRecord(evAgg1, 0);                      // g_X1 ready

    // s2: layer-2 attention prep (needs g_X1 + g_v2), overlaps GEMM2
    cudaStreamWaitEvent(s2, evAgg1, 0);
    cudaStreamWaitEvent(s2, evW2, 0);                // g_v2 from s3
    compute_a_kernel<<<warpNodeBlk, 256, 0, s2>>>(nullptr, HID, 1);
    softmax_kernel<<<warpNodeBlk, 256, 0, s2>>>();
    cudaEventRecord(evS2, s2);                       // softmax2 done

    // main: GEMM2 (needs g_X1 same-stream + W2 fp16 from s3) + final agg
    cudaStreamWaitEvent(0, evW2, 0);
    wmma_gemm_kernel<<<dim3(gemmRows, OUTC / 128), 256, SMB>>>(nullptr, N_NODES, OUTC, 1);
    cudaStreamWaitEvent(0, evS2, 0);
    agg_kernel<OUTC, false, 1><<<warpNodeBlk, 256>>>(out, b2);
}